// round 1
// baseline (speedup 1.0000x reference)
#include <cuda_runtime.h>
#include <math.h>

#define BB 4
#define SS 2048
#define EE 1024
#define HH 16
#define DD 64
#define MM (BB*SS)   // 8192

// Scratch (allocation-free contract: device globals)
__device__ __align__(16) float g_q[(size_t)BB*HH*SS*DD];   // [B,H,S,D]
__device__ __align__(16) float g_k[(size_t)BB*HH*SS*DD];
__device__ __align__(16) float g_v[(size_t)BB*HH*SS*DD];
__device__ __align__(16) float g_ao[(size_t)MM*EE];        // [B,S,E]

// ---------------------------------------------------------------------------
// GEMM: C[M=8192, N=1024] = X[M,K=1024] @ W[K,N] + bias
// MODE 0/1/2: epilogue scatters to g_q/g_k/g_v in [B,H,S,D] layout
// MODE 3:     X = g_ao, plain row-major output to outp (d_out)
// Tile: BM=64, BN=64, BK=16, 256 threads, 4x4 per thread, prefetched.
// ---------------------------------------------------------------------------
template<int MODE>
__global__ __launch_bounds__(256)
void gemm64(const float* __restrict__ Xp, const float* __restrict__ Wp,
            const float* __restrict__ bias, float* __restrict__ outp)
{
    __shared__ __align__(16) float As[16][68];  // [k][m], pad for STS banks + f4 align
    __shared__ __align__(16) float Bs[16][64];  // [k][n]

    const float* __restrict__ X = (MODE == 3) ? g_ao : Xp;

    const int tid = threadIdx.x;
    const int tx = tid & 15;        // 0..15 -> n sub-tile
    const int ty = tid >> 4;        // 0..15 -> m sub-tile
    const int m0 = blockIdx.y * 64;
    const int n0 = blockIdx.x * 64;

    // load mapping
    const int lm = tid >> 2;            // 0..63   X row within tile
    const int lk = (tid & 3) * 4;       // 0/4/8/12 k offset
    const int wk = tid >> 4;            // 0..15   W row within K-slab
    const int wn = (tid & 15) * 4;      // 0..60   W col

    float acc[4][4] = {};

    // prefetch slab 0
    float4 xa = *(const float4*)&X[(size_t)(m0 + lm) * 1024 + lk];
    float4 wb = *(const float4*)&Wp[(size_t)wk * 1024 + n0 + wn];

    for (int k0 = 0; k0 < 1024; k0 += 16) {
        __syncthreads();
        As[lk + 0][lm] = xa.x;
        As[lk + 1][lm] = xa.y;
        As[lk + 2][lm] = xa.z;
        As[lk + 3][lm] = xa.w;
        *(float4*)&Bs[wk][wn] = wb;
        __syncthreads();

        if (k0 + 16 < 1024) {  // prefetch next slab before compute
            xa = *(const float4*)&X[(size_t)(m0 + lm) * 1024 + (k0 + 16) + lk];
            wb = *(const float4*)&Wp[(size_t)(k0 + 16 + wk) * 1024 + n0 + wn];
        }

        #pragma unroll
        for (int kk = 0; kk < 16; kk++) {
            float4 av = *(const float4*)&As[kk][ty * 4];
            float4 bv = *(const float4*)&Bs[kk][tx * 4];
            float ar[4] = {av.x, av.y, av.z, av.w};
            float br[4] = {bv.x, bv.y, bv.z, bv.w};
            #pragma unroll
            for (int r = 0; r < 4; r++)
                #pragma unroll
                for (int c = 0; c < 4; c++)
                    acc[r][c] += ar[r] * br[c];
        }
    }

    // epilogue
    float4 bv4 = *(const float4*)&bias[n0 + tx * 4];
    float bterm[4] = {bv4.x, bv4.y, bv4.z, bv4.w};

    #pragma unroll
    for (int r = 0; r < 4; r++) {
        const int m = m0 + ty * 4 + r;
        float4 o;
        o.x = acc[r][0] + bterm[0];
        o.y = acc[r][1] + bterm[1];
        o.z = acc[r][2] + bterm[2];
        o.w = acc[r][3] + bterm[3];
        if (MODE < 3) {
            // n0 is a multiple of 64 -> whole tile column lies in one head
            const int b = m / SS, s = m % SS;
            const int h = n0 / DD;            // == blockIdx.x
            float* dst = (MODE == 0) ? g_q : (MODE == 1) ? g_k : g_v;
            *(float4*)&dst[((((size_t)b * HH + h) * SS) + s) * DD + tx * 4] = o;
        } else {
            *(float4*)&outp[(size_t)m * 1024 + n0 + tx * 4] = o;
        }
    }
}

// ---------------------------------------------------------------------------
// Flash attention, fp32, causal. One CTA per (b, h, 64-query tile).
// 256 threads: thread = (qrow 0..63, kg 0..3).
//   scores: kg owns 8 keys of the 32-key tile
//   PV:     kg owns 16 of the 64 output dims
// Online softmax state per row replicated across the 4 kg lanes via shfl.
// ---------------------------------------------------------------------------
__global__ __launch_bounds__(256)
void attn_kernel()
{
    __shared__ __align__(16) float Qs [64][65];  // scalar reads, pad vs bank conflicts
    __shared__ __align__(16) float Kst[64][36];  // [d][k], pad 4 keeps f4 alignment
    __shared__ __align__(16) float Vs [32][64];  // [k][d]
    __shared__ __align__(16) float Ps [64][33];  // probs

    const int tid  = threadIdx.x;
    const int qt   = blockIdx.x;       // 0..31
    const int h    = blockIdx.y;
    const int b    = blockIdx.z;
    const int qrow = tid >> 2;         // 0..63
    const int kg   = tid & 3;          // 0..3

    const size_t base = (((size_t)b * HH + h) * SS) * DD;

    // load Q tile, pre-scaled by 1/sqrt(D)
    {
        const int r    = tid >> 2;
        const int dblk = (tid & 3) * 16;
        const float4* src = (const float4*)&g_q[base + (size_t)(qt * 64 + r) * DD + dblk];
        #pragma unroll
        for (int j = 0; j < 4; j++) {
            float4 v = src[j];
            Qs[r][dblk + 4*j + 0] = v.x * 0.125f;
            Qs[r][dblk + 4*j + 1] = v.y * 0.125f;
            Qs[r][dblk + 4*j + 2] = v.z * 0.125f;
            Qs[r][dblk + 4*j + 3] = v.w * 0.125f;
        }
    }

    float m_i = -INFINITY;
    float l_i = 0.0f;
    float acc[16] = {};

    const int qabs = qt * 64 + qrow;
    const int nkt  = 2 * (qt + 1);     // 32-key tiles covering keys [0, (qt+1)*64)

    for (int kt = 0; kt < nkt; kt++) {
        __syncthreads();  // previous PV done before overwriting K/V/P
        {
            const int kr   = tid >> 3;        // 0..31
            const int dblk = (tid & 7) * 8;   // 0..56
            const float* kp = &g_k[base + (size_t)(kt * 32 + kr) * DD + dblk];
            float4 k0 = *(const float4*)kp;
            float4 k1 = *(const float4*)(kp + 4);
            Kst[dblk + 0][kr] = k0.x;  Kst[dblk + 1][kr] = k0.y;
            Kst[dblk + 2][kr] = k0.z;  Kst[dblk + 3][kr] = k0.w;
            Kst[dblk + 4][kr] = k1.x;  Kst[dblk + 5][kr] = k1.y;
            Kst[dblk + 6][kr] = k1.z;  Kst[dblk + 7][kr] = k1.w;
            const float* vp = &g_v[base + (size_t)(kt * 32 + kr) * DD + dblk];
            *(float4*)&Vs[kr][dblk]     = *(const float4*)vp;
            *(float4*)&Vs[kr][dblk + 4] = *(const float4*)(vp + 4);
        }
        __syncthreads();

        // scores: s8[j] = Q[qrow,:] . K[kg*8+j,:]  (Q pre-scaled)
        float s8[8] = {};
        #pragma unroll 8
        for (int d = 0; d < 64; d++) {
            const float qv = Qs[qrow][d];
            float4 ka = *(const float4*)&Kst[d][kg * 8];
            float4 kb = *(const float4*)&Kst[d][kg * 8 + 4];
            float kr8[8] = {ka.x, ka.y, ka.z, ka.w, kb.x, kb.y, kb.z, kb.w};
            #pragma unroll
            for (int j = 0; j < 8; j++) s8[j] += qv * kr8[j];
        }

        // causal mask + online softmax
        const int kbase = kt * 32 + kg * 8;
        float mloc = -INFINITY;
        #pragma unroll
        for (int j = 0; j < 8; j++) {
            if (kbase + j > qabs) s8[j] = -INFINITY;
            mloc = fmaxf(mloc, s8[j]);
        }
        mloc = fmaxf(mloc, __shfl_xor_sync(0xffffffffu, mloc, 1));
        mloc = fmaxf(mloc, __shfl_xor_sync(0xffffffffu, mloc, 2));
        const float m_new = fmaxf(m_i, mloc);
        const float alpha = __expf(m_i - m_new);  // m_i=-inf first tile -> 0

        float psum = 0.0f;
        #pragma unroll
        for (int j = 0; j < 8; j++) {
            const float p = (kbase + j > qabs) ? 0.0f : __expf(s8[j] - m_new);
            Ps[qrow][kg * 8 + j] = p;
            psum += p;
        }
        psum += __shfl_xor_sync(0xffffffffu, psum, 1);
        psum += __shfl_xor_sync(0xffffffffu, psum, 2);
        l_i = l_i * alpha + psum;
        m_i = m_new;
        #pragma unroll
        for (int i = 0; i < 16; i++) acc[i] *= alpha;

        __syncthreads();  // Ps visible to all kg lanes

        // PV: acc[d] += sum_k P[qrow,k] * V[k, kg*16 + d]
        #pragma unroll 4
        for (int k = 0; k < 32; k++) {
            const float p = Ps[qrow][k];
            const float* vr = &Vs[k][kg * 16];
            float4 v0 = *(const float4*)(vr);
            float4 v1 = *(const float4*)(vr + 4);
            float4 v2 = *(const float4*)(vr + 8);
            float4 v3 = *(const float4*)(vr + 12);
            float vv[16] = {v0.x, v0.y, v0.z, v0.w, v1.x, v1.y, v1.z, v1.w,
                            v2.x, v2.y, v2.z, v2.w, v3.x, v3.y, v3.z, v3.w};
            #pragma unroll
            for (int i = 0; i < 16; i++) acc[i] += p * vv[i];
        }
    }

    // normalize and write attention output in [B,S,E] layout
    const float inv_l = 1.0f / l_i;
    float* dst = &g_ao[((size_t)b * SS + qabs) * EE + h * DD + kg * 16];
    #pragma unroll
    for (int j = 0; j < 4; j++) {
        float4 o;
        o.x = acc[4*j + 0] * inv_l;
        o.y = acc[4*j + 1] * inv_l;
        o.z = acc[4*j + 2] * inv_l;
        o.w = acc[4*j + 3] * inv_l;
        *(float4*)&dst[4*j] = o;
    }
}

// ---------------------------------------------------------------------------
extern "C" void kernel_launch(void* const* d_in, const int* in_sizes, int n_in,
                              void* d_out, int out_size)
{
    const float* x  = (const float*)d_in[0];
    const float* Wq = (const float*)d_in[1];
    const float* bq = (const float*)d_in[2];
    const float* Wk = (const float*)d_in[3];
    const float* bk = (const float*)d_in[4];
    const float* Wv = (const float*)d_in[5];
    const float* bv = (const float*)d_in[6];
    const float* Wo = (const float*)d_in[7];
    const float* bo = (const float*)d_in[8];
    float* out = (float*)d_out;

    dim3 gg(EE / 64, MM / 64);   // (16, 128)
    gemm64<0><<<gg, 256>>>(x, Wq, bq, nullptr);
    gemm64<1><<<gg, 256>>>(x, Wk, bk, nullptr);
    gemm64<2><<<gg, 256>>>(x, Wv, bv, nullptr);

    dim3 ag(SS / 64, HH, BB);    // (32, 16, 4)
    attn_kernel<<<ag, 256>>>();

    gemm64<3><<<gg, 256>>>(nullptr, Wo, bo, out);
}

// round 3
// speedup vs baseline: 2.0951x; 2.0951x over previous
#include <cuda_runtime.h>
#include <cuda_bf16.h>
#include <mma.h>
#include <cstdint>
#include <math.h>

using namespace nvcuda;

#define BB 4
#define SS 2048
#define EE 1024
#define HH 16
#define DD 64
#define MM (BB*SS)   // 8192

// ---------------- device scratch (allocation-free contract) ----------------
__device__ __align__(16) float g_q[(size_t)BB*HH*SS*DD];   // [B,H,S,D]
__device__ __align__(16) float g_k[(size_t)BB*HH*SS*DD];
__device__ __align__(16) float g_v[(size_t)BB*HH*SS*DD];
__device__ __align__(16) float g_ao[(size_t)MM*EE];        // [B,S,E]
__device__ __align__(16) __nv_bfloat16 g_xhi[(size_t)MM*EE];   // A hi  [M,K]
__device__ __align__(16) __nv_bfloat16 g_xlo[(size_t)MM*EE];   // A lo
__device__ __align__(16) __nv_bfloat16 g_wthi[(size_t)EE*EE];  // W^T hi [N,K]
__device__ __align__(16) __nv_bfloat16 g_wtlo[(size_t)EE*EE];  // W^T lo

// ---------------- helpers ----------------
__device__ __forceinline__ uint32_t smem_u32(const void* p) {
    uint32_t a;
    asm("{ .reg .u64 t; cvta.to.shared.u64 t, %1; cvt.u32.u64 %0, t; }" : "=r"(a) : "l"(p));
    return a;
}
#define CP_ASYNC16(sa, g)  asm volatile("cp.async.cg.shared.global [%0], [%1], 16;" :: "r"(sa), "l"(g) : "memory")
#define CP_ASYNC_COMMIT()  asm volatile("cp.async.commit_group;" ::: "memory")
#define CP_ASYNC_WAIT0()   asm volatile("cp.async.wait_group 0;" ::: "memory")
#define CP_ASYNC_WAIT1()   asm volatile("cp.async.wait_group 1;" ::: "memory")

__device__ __forceinline__ void split2(float v, __nv_bfloat16& h, __nv_bfloat16& l) {
    h = __float2bfloat16_rn(v);
    l = __float2bfloat16_rn(v - __bfloat162float(h));
}

// ---------------- converters ----------------
// SRC==0: external x pointer; SRC==1: g_ao. Row-major [M,1024] -> bf16 hi/lo.
template<int SRC>
__global__ __launch_bounds__(256) void conv_x(const float* __restrict__ xin) {
    const float* __restrict__ in = (SRC == 0) ? xin : g_ao;
    size_t i = ((size_t)blockIdx.x * 256 + threadIdx.x) * 4;
    float4 v = *(const float4*)(in + i);
    __nv_bfloat16 h0,h1,h2,h3,l0,l1,l2,l3;
    split2(v.x,h0,l0); split2(v.y,h1,l1); split2(v.z,h2,l2); split2(v.w,h3,l3);
    *(__nv_bfloat162*)(g_xhi + i)     = __nv_bfloat162(h0, h1);
    *(__nv_bfloat162*)(g_xhi + i + 2) = __nv_bfloat162(h2, h3);
    *(__nv_bfloat162*)(g_xlo + i)     = __nv_bfloat162(l0, l1);
    *(__nv_bfloat162*)(g_xlo + i + 2) = __nv_bfloat162(l2, l3);
}

// W [K=1024, N=1024] -> W^T hi/lo [N, K] bf16
__global__ __launch_bounds__(256) void conv_w(const float* __restrict__ W) {
    __shared__ float t[32][33];
    const int tx = threadIdx.x & 31, ty = threadIdx.x >> 5;
    const int n0 = blockIdx.x * 32, k0 = blockIdx.y * 32;
    #pragma unroll
    for (int j = 0; j < 4; j++)
        t[ty + 8*j][tx] = W[(size_t)(k0 + ty + 8*j) * 1024 + n0 + tx];
    __syncthreads();
    #pragma unroll
    for (int j = 0; j < 4; j++) {
        float v = t[tx][ty + 8*j];             // = W[k0+tx][n0+ty+8j]
        __nv_bfloat16 h, l; split2(v, h, l);
        size_t o = (size_t)(n0 + ty + 8*j) * 1024 + k0 + tx;
        g_wthi[o] = h;
        g_wtlo[o] = l;
    }
}

// ---------------- WMMA bf16x3 GEMM ----------------
// C[M=8192,N=1024] = X @ W + bias via (hi+lo) splits.
// CTA 128x128, 8 warps in 2x4 -> warp tile 64x32. K-chunk 32, double-buffered.
#define PAD 40                          // bf16 elems per smem row
#define TILE_B   (128 * PAD * 2)        // 10240 bytes (one 128x32 bf16 tile)
#define TILE_E   (128 * PAD)            // elems
#define STAGE_B  (4 * TILE_B)           // Ahi Alo Bhi Blo
#define STAGE_E  (4 * TILE_E)
#define GEMM_SMEM (2 * STAGE_B)         // 81920

__device__ __forceinline__ void stage_load(uint32_t sb,
    const __nv_bfloat16* Ah, const __nv_bfloat16* Al,
    const __nv_bfloat16* Bh, const __nv_bfloat16* Bl, int k0, int tid)
{
    #pragma unroll
    for (int t = 0; t < 2; t++) {
        int u   = tid + t * 256;         // 0..511
        int row = u >> 2;
        int seg = u & 3;
        uint32_t off = (uint32_t)row * (PAD * 2) + seg * 16;
        size_t g = (size_t)row * 1024 + k0 + seg * 8;
        CP_ASYNC16(sb + off,              Ah + g);
        CP_ASYNC16(sb + TILE_B + off,     Al + g);
        CP_ASYNC16(sb + 2 * TILE_B + off, Bh + g);
        CP_ASYNC16(sb + 3 * TILE_B + off, Bl + g);
    }
}

template<int MODE>
__global__ __launch_bounds__(256)
void wgemm(const float* __restrict__ bias, float* __restrict__ outp)
{
    extern __shared__ char smraw[];
    __nv_bfloat16* s = (__nv_bfloat16*)smraw;
    const uint32_t sbase = smem_u32(smraw);

    const int tid  = threadIdx.x;
    const int wid  = tid >> 5, lane = tid & 31;
    const int wm   = wid >> 2, wn = wid & 3;     // 2 x 4 warps
    const int m0   = blockIdx.y * 128;
    const int n0   = blockIdx.x * 128;

    const __nv_bfloat16* Ah = g_xhi + (size_t)m0 * 1024;
    const __nv_bfloat16* Al = g_xlo + (size_t)m0 * 1024;
    const __nv_bfloat16* Bh = g_wthi + (size_t)n0 * 1024;
    const __nv_bfloat16* Bl = g_wtlo + (size_t)n0 * 1024;

    wmma::fragment<wmma::accumulator, 16, 16, 16, float> acc[4][2];
    #pragma unroll
    for (int i = 0; i < 4; i++)
        #pragma unroll
        for (int j = 0; j < 2; j++) wmma::fill_fragment(acc[i][j], 0.0f);

    stage_load(sbase, Ah, Al, Bh, Bl, 0, tid);
    CP_ASYNC_COMMIT();

    for (int kc = 0; kc < 32; kc++) {
        if (kc + 1 < 32) {
            stage_load(sbase + ((kc + 1) & 1) * STAGE_B, Ah, Al, Bh, Bl, (kc + 1) * 32, tid);
            CP_ASYNC_COMMIT();
            CP_ASYNC_WAIT1();
        } else {
            CP_ASYNC_WAIT0();
        }
        __syncthreads();

        const __nv_bfloat16* st = s + (kc & 1) * STAGE_E;
        const __nv_bfloat16* sa_hi = st;
        const __nv_bfloat16* sa_lo = st + TILE_E;
        const __nv_bfloat16* sb_hi = st + 2 * TILE_E;
        const __nv_bfloat16* sb_lo = st + 3 * TILE_E;

        #pragma unroll
        for (int ks = 0; ks < 2; ks++) {
            wmma::fragment<wmma::matrix_a, 16, 16, 16, __nv_bfloat16, wmma::row_major> a[4];
            // hi A pass: ah*bh + ah*bl
            #pragma unroll
            for (int i = 0; i < 4; i++)
                wmma::load_matrix_sync(a[i], sa_hi + (size_t)(wm * 64 + i * 16) * PAD + ks * 16, PAD);
            #pragma unroll
            for (int j = 0; j < 2; j++) {
                wmma::fragment<wmma::matrix_b, 16, 16, 16, __nv_bfloat16, wmma::col_major> bh, bl;
                wmma::load_matrix_sync(bh, sb_hi + (size_t)(wn * 32 + j * 16) * PAD + ks * 16, PAD);
                wmma::load_matrix_sync(bl, sb_lo + (size_t)(wn * 32 + j * 16) * PAD + ks * 16, PAD);
                #pragma unroll
                for (int i = 0; i < 4; i++) wmma::mma_sync(acc[i][j], a[i], bh, acc[i][j]);
                #pragma unroll
                for (int i = 0; i < 4; i++) wmma::mma_sync(acc[i][j], a[i], bl, acc[i][j]);
            }
            // lo A pass: al*bh
            #pragma unroll
            for (int i = 0; i < 4; i++)
                wmma::load_matrix_sync(a[i], sa_lo + (size_t)(wm * 64 + i * 16) * PAD + ks * 16, PAD);
            #pragma unroll
            for (int j = 0; j < 2; j++) {
                wmma::fragment<wmma::matrix_b, 16, 16, 16, __nv_bfloat16, wmma::col_major> bh;
                wmma::load_matrix_sync(bh, sb_hi + (size_t)(wn * 32 + j * 16) * PAD + ks * 16, PAD);
                #pragma unroll
                for (int i = 0; i < 4; i++) wmma::mma_sync(acc[i][j], a[i], bh, acc[i][j]);
            }
        }
        __syncthreads();
    }

    // epilogue: stage warp tile in smem, then vectorized global write + bias
    float* stg = (float*)smraw + (size_t)wid * (64 * 32);
    #pragma unroll
    for (int i = 0; i < 4; i++)
        #pragma unroll
        for (int j = 0; j < 2; j++)
            wmma::store_matrix_sync(stg + i * 16 * 32 + j * 16, acc[i][j], 32, wmma::mem_row_major);
    __syncwarp();

    const int nw0 = n0 + wn * 32;
    #pragma unroll
    for (int l = 0; l < 16; l++) {
        int idx = lane + l * 32;          // 0..511
        int r   = idx >> 3;
        int c4  = (idx & 7) * 4;
        float4 v = *(const float4*)(stg + r * 32 + c4);
        float4 bv = *(const float4*)&bias[nw0 + c4];
        v.x += bv.x; v.y += bv.y; v.z += bv.z; v.w += bv.w;
        const int m = m0 + wm * 64 + r;
        if (MODE < 3) {
            const int b = m >> 11, sq = m & 2047;
            const int h = nw0 >> 6, d0 = (nw0 & 63) + c4;
            float* base = (MODE == 0) ? g_q : (MODE == 1) ? g_k : g_v;
            *(float4*)&base[((((size_t)b * HH + h) * SS) + sq) * DD + d0] = v;
        } else {
            *(float4*)&outp[(size_t)m * 1024 + nw0 + c4] = v;
        }
    }
}

// ---------------- flash attention, fp32, register-tiled ----------------
// CTA: 64 q-rows, k-tiles of 64. 128 threads: (qg=tid>>3: 4 q-rows, kl=tid&7).
#define AP 68
#define ATTN_SMEM (4 * 64 * AP * 4)

__global__ __launch_bounds__(128)
void attn2()
{
    extern __shared__ float sm[];
    float* Qt  = sm;             // [64d][AP]  Qt[d][q]
    float* Kst = Qt  + 64 * AP;  // [64d][AP]  Kst[d][k]
    float* Vs  = Kst + 64 * AP;  // [64k][AP]  Vs[k][d]
    float* Pt  = Vs  + 64 * AP;  // [64k][AP]  Pt[k][q]

    const int tid = threadIdx.x;
    const int qt = blockIdx.x, h = blockIdx.y, b = blockIdx.z;
    const int qg = tid >> 3;    // 0..15
    const int kl = tid & 7;     // 0..7

    const size_t base = (((size_t)b * HH + h) * SS) * DD;

    {
        const int r = tid >> 1, dblk = (tid & 1) * 32;
        const float4* src = (const float4*)&g_q[base + (size_t)(qt * 64 + r) * DD + dblk];
        #pragma unroll
        for (int j = 0; j < 8; j++) {
            float4 v = src[j];
            Qt[(dblk + 4*j + 0) * AP + r] = v.x * 0.125f;
            Qt[(dblk + 4*j + 1) * AP + r] = v.y * 0.125f;
            Qt[(dblk + 4*j + 2) * AP + r] = v.z * 0.125f;
            Qt[(dblk + 4*j + 3) * AP + r] = v.w * 0.125f;
        }
    }

    float m_i[4], l_i[4], acc[4][8];
    #pragma unroll
    for (int i = 0; i < 4; i++) {
        m_i[i] = -INFINITY; l_i[i] = 0.0f;
        #pragma unroll
        for (int c = 0; c < 8; c++) acc[i][c] = 0.0f;
    }

    for (int kt = 0; kt <= qt; kt++) {
        __syncthreads();
        {
            const int r = tid >> 1, dblk = (tid & 1) * 32;
            const float4* ks = (const float4*)&g_k[base + (size_t)(kt * 64 + r) * DD + dblk];
            const float4* vs = (const float4*)&g_v[base + (size_t)(kt * 64 + r) * DD + dblk];
            #pragma unroll
            for (int j = 0; j < 8; j++) {
                float4 kv = ks[j];
                Kst[(dblk + 4*j + 0) * AP + r] = kv.x;
                Kst[(dblk + 4*j + 1) * AP + r] = kv.y;
                Kst[(dblk + 4*j + 2) * AP + r] = kv.z;
                Kst[(dblk + 4*j + 3) * AP + r] = kv.w;
                *(float4*)&Vs[r * AP + dblk + 4*j] = vs[j];
            }
        }
        __syncthreads();

        float s[4][8];
        #pragma unroll
        for (int i = 0; i < 4; i++)
            #pragma unroll
            for (int j = 0; j < 8; j++) s[i][j] = 0.0f;

        #pragma unroll 4
        for (int d = 0; d < 64; d++) {
            float4 q4 = *(const float4*)&Qt[d * AP + qg * 4];
            float4 ka = *(const float4*)&Kst[d * AP + kl * 8];
            float4 kb = *(const float4*)&Kst[d * AP + kl * 8 + 4];
            float qv[4] = {q4.x, q4.y, q4.z, q4.w};
            float kv[8] = {ka.x, ka.y, ka.z, ka.w, kb.x, kb.y, kb.z, kb.w};
            #pragma unroll
            for (int i = 0; i < 4; i++)
                #pragma unroll
                for (int j = 0; j < 8; j++) s[i][j] += qv[i] * kv[j];
        }

        if (kt == qt) {
            #pragma unroll
            for (int i = 0; i < 4; i++)
                #pragma unroll
                for (int j = 0; j < 8; j++)
                    if (kl * 8 + j > qg * 4 + i) s[i][j] = -INFINITY;
        }

        #pragma unroll
        for (int i = 0; i < 4; i++) {
            float mx = s[i][0];
            #pragma unroll
            for (int j = 1; j < 8; j++) mx = fmaxf(mx, s[i][j]);
            mx = fmaxf(mx, __shfl_xor_sync(0xffffffffu, mx, 1));
            mx = fmaxf(mx, __shfl_xor_sync(0xffffffffu, mx, 2));
            mx = fmaxf(mx, __shfl_xor_sync(0xffffffffu, mx, 4));
            const float mnew  = fmaxf(m_i[i], mx);
            const float alpha = __expf(m_i[i] - mnew);
            m_i[i] = mnew;
            float ps = 0.0f;
            #pragma unroll
            for (int j = 0; j < 8; j++) {
                float p = __expf(s[i][j] - mnew);
                s[i][j] = p;
                ps += p;
            }
            ps += __shfl_xor_sync(0xffffffffu, ps, 1);
            ps += __shfl_xor_sync(0xffffffffu, ps, 2);
            ps += __shfl_xor_sync(0xffffffffu, ps, 4);
            l_i[i] = l_i[i] * alpha + ps;
            #pragma unroll
            for (int c = 0; c < 8; c++) acc[i][c] *= alpha;
        }

        #pragma unroll
        for (int j = 0; j < 8; j++) {
            float4 o = make_float4(s[0][j], s[1][j], s[2][j], s[3][j]);
            *(float4*)&Pt[(kl * 8 + j) * AP + qg * 4] = o;
        }
        __syncwarp();

        #pragma unroll 4
        for (int k = 0; k < 64; k++) {
            float4 p4 = *(const float4*)&Pt[k * AP + qg * 4];
            float4 va = *(const float4*)&Vs[k * AP + kl * 8];
            float4 vb = *(const float4*)&Vs[k * AP + kl * 8 + 4];
            float pv[4] = {p4.x, p4.y, p4.z, p4.w};
            float vv[8] = {va.x, va.y, va.z, va.w, vb.x, vb.y, vb.z, vb.w};
            #pragma unroll
            for (int i = 0; i < 4; i++)
                #pragma unroll
                for (int c = 0; c < 8; c++) acc[i][c] += pv[i] * vv[c];
        }
    }

    #pragma unroll
    for (int i = 0; i < 4; i++) {
        const float inv = 1.0f / l_i[i];
        const int row = qt * 64 + qg * 4 + i;
        float* dst = &g_ao[((size_t)b * SS + row) * EE + h * DD + kl * 8];
        float4 oa, ob;
        oa.x = acc[i][0]*inv; oa.y = acc[i][1]*inv; oa.z = acc[i][2]*inv; oa.w = acc[i][3]*inv;
        ob.x = acc[i][4]*inv; ob.y = acc[i][5]*inv; ob.z = acc[i][6]*inv; ob.w = acc[i][7]*inv;
        *(float4*)dst = oa;
        *(float4*)(dst + 4) = ob;
    }
}

// ---------------------------------------------------------------------------
extern "C" void kernel_launch(void* const* d_in, const int* in_sizes, int n_in,
                              void* d_out, int out_size)
{
    const float* x  = (const float*)d_in[0];
    const float* Wq = (const float*)d_in[1];
    const float* bq = (const float*)d_in[2];
    const float* Wk = (const float*)d_in[3];
    const float* bk = (const float*)d_in[4];
    const float* Wv = (const float*)d_in[5];
    const float* bv = (const float*)d_in[6];
    const float* Wo = (const float*)d_in[7];
    const float* bo = (const float*)d_in[8];
    float* out = (float*)d_out;

    cudaFuncSetAttribute(wgemm<0>, cudaFuncAttributeMaxDynamicSharedMemorySize, GEMM_SMEM);
    cudaFuncSetAttribute(wgemm<1>, cudaFuncAttributeMaxDynamicSharedMemorySize, GEMM_SMEM);
    cudaFuncSetAttribute(wgemm<2>, cudaFuncAttributeMaxDynamicSharedMemorySize, GEMM_SMEM);
    cudaFuncSetAttribute(wgemm<3>, cudaFuncAttributeMaxDynamicSharedMemorySize, GEMM_SMEM);
    cudaFuncSetAttribute(attn2,    cudaFuncAttributeMaxDynamicSharedMemorySize, ATTN_SMEM);

    const dim3 gg(EE / 128, MM / 128);   // (8, 64)
    const dim3 wg(32, 32);

    conv_x<0><<<MM * EE / 1024, 256>>>(x);
    conv_w<<<wg, 256>>>(Wq);
    wgemm<0><<<gg, 256, GEMM_SMEM>>>(bq, nullptr);
    conv_w<<<wg, 256>>>(Wk);
    wgemm<1><<<gg, 256, GEMM_SMEM>>>(bk, nullptr);
    conv_w<<<wg, 256>>>(Wv);
    wgemm<2><<<gg, 256, GEMM_SMEM>>>(bv, nullptr);

    attn2<<<dim3(SS / 64, HH, BB), 128, ATTN_SMEM>>>();

    conv_x<1><<<MM * EE / 1024, 256>>>(nullptr);
    conv_w<<<wg, 256>>>(Wo);
    wgemm<3><<<gg, 256, GEMM_SMEM>>>(bo, out);
}

// round 4
// speedup vs baseline: 3.2893x; 1.5700x over previous
#include <cuda_runtime.h>
#include <cuda_bf16.h>
#include <mma.h>
#include <cstdint>
#include <math.h>

using namespace nvcuda;

#define BB 4
#define SS 2048
#define EE 1024
#define HH 16
#define DD 64
#define MM (BB*SS)   // 8192

// ---------------- device scratch (allocation-free contract) ----------------
__device__ __align__(16) __nv_bfloat16 g_xhi[(size_t)MM*EE];   // A hi [M,K]
__device__ __align__(16) __nv_bfloat16 g_xlo[(size_t)MM*EE];   // A lo
__device__ __align__(16) __nv_bfloat16 g_wthi[(size_t)EE*EE];  // W^T hi [N,K]
__device__ __align__(16) __nv_bfloat16 g_wtlo[(size_t)EE*EE];  // W^T lo
// Q/K/V as bf16 hi/lo in [B,H,S,D] (Q pre-scaled by 1/sqrt(D))
__device__ __align__(16) __nv_bfloat16 g_qhi[(size_t)BB*HH*SS*DD];
__device__ __align__(16) __nv_bfloat16 g_qlo[(size_t)BB*HH*SS*DD];
__device__ __align__(16) __nv_bfloat16 g_khi[(size_t)BB*HH*SS*DD];
__device__ __align__(16) __nv_bfloat16 g_klo[(size_t)BB*HH*SS*DD];
__device__ __align__(16) __nv_bfloat16 g_vhi[(size_t)BB*HH*SS*DD];
__device__ __align__(16) __nv_bfloat16 g_vlo[(size_t)BB*HH*SS*DD];

// ---------------- helpers ----------------
__device__ __forceinline__ uint32_t smem_u32(const void* p) {
    uint32_t a;
    asm("{ .reg .u64 t; cvta.to.shared.u64 t, %1; cvt.u32.u64 %0, t; }" : "=r"(a) : "l"(p));
    return a;
}
#define CP_ASYNC16(sa, g)  asm volatile("cp.async.cg.shared.global [%0], [%1], 16;" :: "r"(sa), "l"(g) : "memory")
#define CP_ASYNC_COMMIT()  asm volatile("cp.async.commit_group;" ::: "memory")
#define CP_ASYNC_WAIT0()   asm volatile("cp.async.wait_group 0;" ::: "memory")
#define CP_ASYNC_WAIT1()   asm volatile("cp.async.wait_group 1;" ::: "memory")

__device__ __forceinline__ void split2(float v, __nv_bfloat16& h, __nv_bfloat16& l) {
    h = __float2bfloat16_rn(v);
    l = __float2bfloat16_rn(v - __bfloat162float(h));
}

// ---------------- converters ----------------
__global__ __launch_bounds__(256) void conv_x(const float* __restrict__ in) {
    size_t i = ((size_t)blockIdx.x * 256 + threadIdx.x) * 4;
    float4 v = *(const float4*)(in + i);
    __nv_bfloat16 h0,h1,h2,h3,l0,l1,l2,l3;
    split2(v.x,h0,l0); split2(v.y,h1,l1); split2(v.z,h2,l2); split2(v.w,h3,l3);
    *(__nv_bfloat162*)(g_xhi + i)     = __nv_bfloat162(h0, h1);
    *(__nv_bfloat162*)(g_xhi + i + 2) = __nv_bfloat162(h2, h3);
    *(__nv_bfloat162*)(g_xlo + i)     = __nv_bfloat162(l0, l1);
    *(__nv_bfloat162*)(g_xlo + i + 2) = __nv_bfloat162(l2, l3);
}

__global__ __launch_bounds__(256) void conv_w(const float* __restrict__ W) {
    __shared__ float t[32][33];
    const int tx = threadIdx.x & 31, ty = threadIdx.x >> 5;
    const int n0 = blockIdx.x * 32, k0 = blockIdx.y * 32;
    #pragma unroll
    for (int j = 0; j < 4; j++)
        t[ty + 8*j][tx] = W[(size_t)(k0 + ty + 8*j) * 1024 + n0 + tx];
    __syncthreads();
    #pragma unroll
    for (int j = 0; j < 4; j++) {
        float v = t[tx][ty + 8*j];
        __nv_bfloat16 hh, ll; split2(v, hh, ll);
        size_t o = (size_t)(n0 + ty + 8*j) * 1024 + k0 + tx;
        g_wthi[o] = hh;
        g_wtlo[o] = ll;
    }
}

// ---------------- WMMA bf16x3 GEMM ----------------
#define PAD 40
#define TILE_B   (128 * PAD * 2)
#define TILE_E   (128 * PAD)
#define STAGE_B  (4 * TILE_B)
#define STAGE_E  (4 * TILE_E)
#define GEMM_SMEM (2 * STAGE_B)

__device__ __forceinline__ void stage_load(uint32_t sb,
    const __nv_bfloat16* Ah, const __nv_bfloat16* Al,
    const __nv_bfloat16* Bh, const __nv_bfloat16* Bl, int k0, int tid)
{
    #pragma unroll
    for (int t = 0; t < 2; t++) {
        int u   = tid + t * 256;
        int row = u >> 2;
        int seg = u & 3;
        uint32_t off = (uint32_t)row * (PAD * 2) + seg * 16;
        size_t g = (size_t)row * 1024 + k0 + seg * 8;
        CP_ASYNC16(sb + off,              Ah + g);
        CP_ASYNC16(sb + TILE_B + off,     Al + g);
        CP_ASYNC16(sb + 2 * TILE_B + off, Bh + g);
        CP_ASYNC16(sb + 3 * TILE_B + off, Bl + g);
    }
}

template<int MODE>
__global__ __launch_bounds__(256)
void wgemm(const float* __restrict__ bias, float* __restrict__ outp)
{
    extern __shared__ char smraw[];
    __nv_bfloat16* s = (__nv_bfloat16*)smraw;
    const uint32_t sbase = smem_u32(smraw);

    const int tid  = threadIdx.x;
    const int wid  = tid >> 5, lane = tid & 31;
    const int wm   = wid >> 2, wn = wid & 3;
    const int m0   = blockIdx.y * 128;
    const int n0   = blockIdx.x * 128;

    const __nv_bfloat16* Ah = g_xhi + (size_t)m0 * 1024;
    const __nv_bfloat16* Al = g_xlo + (size_t)m0 * 1024;
    const __nv_bfloat16* Bh = g_wthi + (size_t)n0 * 1024;
    const __nv_bfloat16* Bl = g_wtlo + (size_t)n0 * 1024;

    wmma::fragment<wmma::accumulator, 16, 16, 16, float> acc[4][2];
    #pragma unroll
    for (int i = 0; i < 4; i++)
        #pragma unroll
        for (int j = 0; j < 2; j++) wmma::fill_fragment(acc[i][j], 0.0f);

    stage_load(sbase, Ah, Al, Bh, Bl, 0, tid);
    CP_ASYNC_COMMIT();

    for (int kc = 0; kc < 32; kc++) {
        if (kc + 1 < 32) {
            stage_load(sbase + ((kc + 1) & 1) * STAGE_B, Ah, Al, Bh, Bl, (kc + 1) * 32, tid);
            CP_ASYNC_COMMIT();
            CP_ASYNC_WAIT1();
        } else {
            CP_ASYNC_WAIT0();
        }
        __syncthreads();

        const __nv_bfloat16* st = s + (kc & 1) * STAGE_E;
        const __nv_bfloat16* sa_hi = st;
        const __nv_bfloat16* sa_lo = st + TILE_E;
        const __nv_bfloat16* sb_hi = st + 2 * TILE_E;
        const __nv_bfloat16* sb_lo = st + 3 * TILE_E;

        #pragma unroll
        for (int ks = 0; ks < 2; ks++) {
            wmma::fragment<wmma::matrix_a, 16, 16, 16, __nv_bfloat16, wmma::row_major> a[4];
            #pragma unroll
            for (int i = 0; i < 4; i++)
                wmma::load_matrix_sync(a[i], sa_hi + (size_t)(wm * 64 + i * 16) * PAD + ks * 16, PAD);
            #pragma unroll
            for (int j = 0; j < 2; j++) {
                wmma::fragment<wmma::matrix_b, 16, 16, 16, __nv_bfloat16, wmma::col_major> bh, bl;
                wmma::load_matrix_sync(bh, sb_hi + (size_t)(wn * 32 + j * 16) * PAD + ks * 16, PAD);
                wmma::load_matrix_sync(bl, sb_lo + (size_t)(wn * 32 + j * 16) * PAD + ks * 16, PAD);
                #pragma unroll
                for (int i = 0; i < 4; i++) wmma::mma_sync(acc[i][j], a[i], bh, acc[i][j]);
                #pragma unroll
                for (int i = 0; i < 4; i++) wmma::mma_sync(acc[i][j], a[i], bl, acc[i][j]);
            }
            #pragma unroll
            for (int i = 0; i < 4; i++)
                wmma::load_matrix_sync(a[i], sa_lo + (size_t)(wm * 64 + i * 16) * PAD + ks * 16, PAD);
            #pragma unroll
            for (int j = 0; j < 2; j++) {
                wmma::fragment<wmma::matrix_b, 16, 16, 16, __nv_bfloat16, wmma::col_major> bh;
                wmma::load_matrix_sync(bh, sb_hi + (size_t)(wn * 32 + j * 16) * PAD + ks * 16, PAD);
                #pragma unroll
                for (int i = 0; i < 4; i++) wmma::mma_sync(acc[i][j], a[i], bh, acc[i][j]);
            }
        }
        __syncthreads();
    }

    // epilogue: stage warp tile, vectorized write
    float* stg = (float*)smraw + (size_t)wid * (64 * 32);
    #pragma unroll
    for (int i = 0; i < 4; i++)
        #pragma unroll
        for (int j = 0; j < 2; j++)
            wmma::store_matrix_sync(stg + i * 16 * 32 + j * 16, acc[i][j], 32, wmma::mem_row_major);
    __syncwarp();

    const int nw0 = n0 + wn * 32;
    #pragma unroll
    for (int l = 0; l < 16; l++) {
        int idx = lane + l * 32;
        int r   = idx >> 3;
        int c4  = (idx & 7) * 4;
        float4 v = *(const float4*)(stg + r * 32 + c4);
        float4 bv = *(const float4*)&bias[nw0 + c4];
        v.x += bv.x; v.y += bv.y; v.z += bv.z; v.w += bv.w;
        const int m = m0 + wm * 64 + r;
        if (MODE < 3) {
            if (MODE == 0) { v.x *= 0.125f; v.y *= 0.125f; v.z *= 0.125f; v.w *= 0.125f; }
            const int b = m >> 11, sq = m & 2047;
            const int hd = nw0 >> 6, d0 = (nw0 & 63) + c4;
            __nv_bfloat16* dh = ((MODE == 0) ? g_qhi : (MODE == 1) ? g_khi : g_vhi)
                                + ((((size_t)b * HH + hd) * SS) + sq) * DD + d0;
            __nv_bfloat16* dl = ((MODE == 0) ? g_qlo : (MODE == 1) ? g_klo : g_vlo)
                                + ((((size_t)b * HH + hd) * SS) + sq) * DD + d0;
            __nv_bfloat16 h0,h1,h2,h3,l0,l1,l2,l3;
            split2(v.x,h0,l0); split2(v.y,h1,l1); split2(v.z,h2,l2); split2(v.w,h3,l3);
            *(__nv_bfloat162*)dh       = __nv_bfloat162(h0, h1);
            *(__nv_bfloat162*)(dh + 2) = __nv_bfloat162(h2, h3);
            *(__nv_bfloat162*)dl       = __nv_bfloat162(l0, l1);
            *(__nv_bfloat162*)(dl + 2) = __nv_bfloat162(l2, l3);
        } else {
            *(float4*)&outp[(size_t)m * 1024 + nw0 + c4] = v;
        }
    }
}

// ---------------- WMMA flash attention ----------------
// CTA: 64 queries, 4 warps (128 thr). k-tiles of 64. bf16x3 HMMA for S and PV.
#define BF_LD 72
#define F_LD  68
#define ATTN_SMEM (8 * 64 * BF_LD * 2 + 2 * 64 * F_LD * 4)   // 108544

__global__ __launch_bounds__(128)
void attn3()
{
    extern __shared__ char smraw[];
    __nv_bfloat16* sQh = (__nv_bfloat16*)smraw;
    __nv_bfloat16* sQl = sQh + 64 * BF_LD;
    __nv_bfloat16* sKh = sQl + 64 * BF_LD;
    __nv_bfloat16* sKl = sKh + 64 * BF_LD;
    __nv_bfloat16* sVh = sKl + 64 * BF_LD;
    __nv_bfloat16* sVl = sVh + 64 * BF_LD;
    __nv_bfloat16* sPh = sVl + 64 * BF_LD;
    __nv_bfloat16* sPl = sPh + 64 * BF_LD;
    float* sS = (float*)(sPl + 64 * BF_LD);   // scores / PV-delta staging
    float* sO = sS + 64 * F_LD;               // output accumulator

    const int tid  = threadIdx.x;
    const int warp = tid >> 5;
    const int qt = blockIdx.x, hh = blockIdx.y, bb = blockIdx.z;
    const int row  = tid >> 1;        // softmax row ownership
    const int half = tid & 1;

    const size_t qbase = (((size_t)bb * HH + hh) * SS + (size_t)qt * 64) * DD;

    // load Q hi/lo tile
    #pragma unroll
    for (int i = 0; i < 4; i++) {
        int u = i * 128 + tid;
        int r = u >> 3, sg = u & 7;
        CP_ASYNC16(smem_u32(sQh + r * BF_LD + sg * 8), g_qhi + qbase + r * 64 + sg * 8);
        CP_ASYNC16(smem_u32(sQl + r * BF_LD + sg * 8), g_qlo + qbase + r * 64 + sg * 8);
    }
    CP_ASYNC_COMMIT();

    for (int i = tid; i < 64 * F_LD; i += 128) sO[i] = 0.0f;

    CP_ASYNC_WAIT0();
    __syncthreads();

    // persistent Q a-fragments
    wmma::fragment<wmma::matrix_a, 16, 16, 16, __nv_bfloat16, wmma::row_major> aQh[4], aQl[4];
    #pragma unroll
    for (int kk = 0; kk < 4; kk++) {
        wmma::load_matrix_sync(aQh[kk], sQh + (size_t)(warp * 16) * BF_LD + kk * 16, BF_LD);
        wmma::load_matrix_sync(aQl[kk], sQl + (size_t)(warp * 16) * BF_LD + kk * 16, BF_LD);
    }

    float m_i = -INFINITY, l_i = 0.0f;

    for (int kt = 0; kt <= qt; kt++) {
        __syncthreads();   // protect K/V/S/P from previous iteration
        const size_t kb = (((size_t)bb * HH + hh) * SS + (size_t)kt * 64) * DD;
        #pragma unroll
        for (int i = 0; i < 4; i++) {
            int u = i * 128 + tid;
            int r = u >> 3, sg = u & 7;
            int go = r * 64 + sg * 8;
            int so = r * BF_LD + sg * 8;
            CP_ASYNC16(smem_u32(sKh + so), g_khi + kb + go);
            CP_ASYNC16(smem_u32(sKl + so), g_klo + kb + go);
            CP_ASYNC16(smem_u32(sVh + so), g_vhi + kb + go);
            CP_ASYNC16(smem_u32(sVl + so), g_vlo + kb + go);
        }
        CP_ASYNC_COMMIT();
        CP_ASYNC_WAIT0();
        __syncthreads();

        // ---- scores: S[16 rows][64 keys] per warp ----
        {
            wmma::fragment<wmma::accumulator, 16, 16, 16, float> accS[4];
            #pragma unroll
            for (int j = 0; j < 4; j++) wmma::fill_fragment(accS[j], 0.0f);
            #pragma unroll
            for (int kk = 0; kk < 4; kk++) {
                #pragma unroll
                for (int j = 0; j < 4; j++) {
                    wmma::fragment<wmma::matrix_b, 16, 16, 16, __nv_bfloat16, wmma::col_major> bh, bl;
                    wmma::load_matrix_sync(bh, sKh + (size_t)(j * 16) * BF_LD + kk * 16, BF_LD);
                    wmma::load_matrix_sync(bl, sKl + (size_t)(j * 16) * BF_LD + kk * 16, BF_LD);
                    wmma::mma_sync(accS[j], aQh[kk], bh, accS[j]);
                    wmma::mma_sync(accS[j], aQh[kk], bl, accS[j]);
                    wmma::mma_sync(accS[j], aQl[kk], bh, accS[j]);
                }
            }
            #pragma unroll
            for (int j = 0; j < 4; j++)
                wmma::store_matrix_sync(sS + (size_t)(warp * 16) * F_LD + j * 16, accS[j], F_LD, wmma::mem_row_major);
        }
        __syncthreads();

        // ---- softmax (2 threads per row) ----
        {
            const float* srow = sS + (size_t)row * F_LD + half * 32;
            const bool diag = (kt == qt);
            float mx = -INFINITY;
            #pragma unroll
            for (int c8 = 0; c8 < 8; c8++) {
                float4 v = *(const float4*)(srow + 4 * c8);
                if (diag) {
                    int c0 = half * 32 + 4 * c8;
                    if (c0 + 0 > row) v.x = -INFINITY;
                    if (c0 + 1 > row) v.y = -INFINITY;
                    if (c0 + 2 > row) v.z = -INFINITY;
                    if (c0 + 3 > row) v.w = -INFINITY;
                }
                mx = fmaxf(mx, fmaxf(fmaxf(v.x, v.y), fmaxf(v.z, v.w)));
            }
            mx = fmaxf(mx, __shfl_xor_sync(0xffffffffu, mx, 1));
            const float m_new = fmaxf(m_i, mx);
            const float alpha = __expf(m_i - m_new);
            float ps = 0.0f;
            __nv_bfloat16* ph = sPh + (size_t)row * BF_LD + half * 32;
            __nv_bfloat16* pl = sPl + (size_t)row * BF_LD + half * 32;
            #pragma unroll
            for (int c8 = 0; c8 < 8; c8++) {
                float4 v = *(const float4*)(srow + 4 * c8);
                int c0 = half * 32 + 4 * c8;
                float p0 = (diag && c0 + 0 > row) ? 0.0f : __expf(v.x - m_new);
                float p1 = (diag && c0 + 1 > row) ? 0.0f : __expf(v.y - m_new);
                float p2 = (diag && c0 + 2 > row) ? 0.0f : __expf(v.z - m_new);
                float p3 = (diag && c0 + 3 > row) ? 0.0f : __expf(v.w - m_new);
                ps += p0 + p1 + p2 + p3;
                __nv_bfloat16 a0,a1,a2,a3,b0,b1,b2,b3;
                split2(p0,a0,b0); split2(p1,a1,b1); split2(p2,a2,b2); split2(p3,a3,b3);
                *(__nv_bfloat162*)(ph + 4*c8)     = __nv_bfloat162(a0, a1);
                *(__nv_bfloat162*)(ph + 4*c8 + 2) = __nv_bfloat162(a2, a3);
                *(__nv_bfloat162*)(pl + 4*c8)     = __nv_bfloat162(b0, b1);
                *(__nv_bfloat162*)(pl + 4*c8 + 2) = __nv_bfloat162(b2, b3);
            }
            ps += __shfl_xor_sync(0xffffffffu, ps, 1);
            l_i = l_i * alpha + ps;
            m_i = m_new;
            // rescale O row
            float* orow = sO + (size_t)row * F_LD + half * 32;
            #pragma unroll
            for (int c8 = 0; c8 < 8; c8++) {
                float4 ov = *(const float4*)(orow + 4 * c8);
                ov.x *= alpha; ov.y *= alpha; ov.z *= alpha; ov.w *= alpha;
                *(float4*)(orow + 4 * c8) = ov;
            }
        }
        __syncthreads();

        // ---- PV: delta[16 rows][64 dims] per warp ----
        {
            wmma::fragment<wmma::accumulator, 16, 16, 16, float> accO[4];
            #pragma unroll
            for (int j = 0; j < 4; j++) wmma::fill_fragment(accO[j], 0.0f);
            #pragma unroll
            for (int kk = 0; kk < 4; kk++) {
                wmma::fragment<wmma::matrix_a, 16, 16, 16, __nv_bfloat16, wmma::row_major> aph, apl;
                wmma::load_matrix_sync(aph, sPh + (size_t)(warp * 16) * BF_LD + kk * 16, BF_LD);
                wmma::load_matrix_sync(apl, sPl + (size_t)(warp * 16) * BF_LD + kk * 16, BF_LD);
                #pragma unroll
                for (int j = 0; j < 4; j++) {
                    wmma::fragment<wmma::matrix_b, 16, 16, 16, __nv_bfloat16, wmma::row_major> bvh, bvl;
                    wmma::load_matrix_sync(bvh, sVh + (size_t)(kk * 16) * BF_LD + j * 16, BF_LD);
                    wmma::load_matrix_sync(bvl, sVl + (size_t)(kk * 16) * BF_LD + j * 16, BF_LD);
                    wmma::mma_sync(accO[j], aph, bvh, accO[j]);
                    wmma::mma_sync(accO[j], aph, bvl, accO[j]);
                    wmma::mma_sync(accO[j], apl, bvh, accO[j]);
                }
            }
            #pragma unroll
            for (int j = 0; j < 4; j++)
                wmma::store_matrix_sync(sS + (size_t)(warp * 16) * F_LD + j * 16, accO[j], F_LD, wmma::mem_row_major);
        }
        __syncthreads();

        // ---- O += delta ----
        {
            const float* drow = sS + (size_t)row * F_LD + half * 32;
            float* orow = sO + (size_t)row * F_LD + half * 32;
            #pragma unroll
            for (int c8 = 0; c8 < 8; c8++) {
                float4 d = *(const float4*)(drow + 4 * c8);
                float4 o = *(const float4*)(orow + 4 * c8);
                o.x += d.x; o.y += d.y; o.z += d.z; o.w += d.w;
                *(float4*)(orow + 4 * c8) = o;
            }
        }
    }

    // epilogue: normalize, split, write directly as A-operand for O-projection
    {
        const float inv = 1.0f / l_i;
        const float* orow = sO + (size_t)row * F_LD + half * 32;
        const size_t go = ((size_t)bb * SS + (size_t)qt * 64 + row) * EE + hh * DD + half * 32;
        #pragma unroll
        for (int c8 = 0; c8 < 8; c8++) {
            float4 v = *(const float4*)(orow + 4 * c8);
            v.x *= inv; v.y *= inv; v.z *= inv; v.w *= inv;
            __nv_bfloat16 h0,h1,h2,h3,l0,l1,l2,l3;
            split2(v.x,h0,l0); split2(v.y,h1,l1); split2(v.z,h2,l2); split2(v.w,h3,l3);
            *(__nv_bfloat162*)(g_xhi + go + 4*c8)     = __nv_bfloat162(h0, h1);
            *(__nv_bfloat162*)(g_xhi + go + 4*c8 + 2) = __nv_bfloat162(h2, h3);
            *(__nv_bfloat162*)(g_xlo + go + 4*c8)     = __nv_bfloat162(l0, l1);
            *(__nv_bfloat162*)(g_xlo + go + 4*c8 + 2) = __nv_bfloat162(l2, l3);
        }
    }
}

// ---------------------------------------------------------------------------
extern "C" void kernel_launch(void* const* d_in, const int* in_sizes, int n_in,
                              void* d_out, int out_size)
{
    const float* x  = (const float*)d_in[0];
    const float* Wq = (const float*)d_in[1];
    const float* bq = (const float*)d_in[2];
    const float* Wk = (const float*)d_in[3];
    const float* bk = (const float*)d_in[4];
    const float* Wv = (const float*)d_in[5];
    const float* bv = (const float*)d_in[6];
    const float* Wo = (const float*)d_in[7];
    const float* bo = (const float*)d_in[8];
    float* out = (float*)d_out;

    cudaFuncSetAttribute(wgemm<0>, cudaFuncAttributeMaxDynamicSharedMemorySize, GEMM_SMEM);
    cudaFuncSetAttribute(wgemm<1>, cudaFuncAttributeMaxDynamicSharedMemorySize, GEMM_SMEM);
    cudaFuncSetAttribute(wgemm<2>, cudaFuncAttributeMaxDynamicSharedMemorySize, GEMM_SMEM);
    cudaFuncSetAttribute(wgemm<3>, cudaFuncAttributeMaxDynamicSharedMemorySize, GEMM_SMEM);
    cudaFuncSetAttribute(attn3,    cudaFuncAttributeMaxDynamicSharedMemorySize, ATTN_SMEM);

    const dim3 gg(EE / 128, MM / 128);   // (8, 64)
    const dim3 wg(32, 32);

    conv_x<<<MM * EE / 1024, 256>>>(x);
    conv_w<<<wg, 256>>>(Wq);
    wgemm<0><<<gg, 256, GEMM_SMEM>>>(bq, nullptr);
    conv_w<<<wg, 256>>>(Wk);
    wgemm<1><<<gg, 256, GEMM_SMEM>>>(bk, nullptr);
    conv_w<<<wg, 256>>>(Wv);
    wgemm<2><<<gg, 256, GEMM_SMEM>>>(bv, nullptr);

    attn3<<<dim3(SS / 64, HH, BB), 128, ATTN_SMEM>>>();

    conv_w<<<wg, 256>>>(Wo);
    wgemm<3><<<gg, 256, GEMM_SMEM>>>(bo, out);
}

// round 5
// speedup vs baseline: 5.2090x; 1.5836x over previous
#include <cuda_runtime.h>
#include <cuda_fp16.h>
#include <mma.h>
#include <cstdint>
#include <math.h>

using namespace nvcuda;

#define BB 4
#define SS 2048
#define EE 1024
#define HH 16
#define DD 64
#define MM (BB*SS)   // 8192

// ---------------- device scratch (allocation-free contract) ----------------
__device__ __align__(16) __half g_xh[(size_t)MM*EE];           // A operand fp16 [M,K]; attn writes output here
__device__ __align__(16) __half g_wth[4*(size_t)EE*EE];        // W^T hi [4][N,K]
__device__ __align__(16) __half g_wtl[4*(size_t)EE*EE];        // W^T lo
__device__ __align__(16) __half g_qh[(size_t)BB*HH*SS*DD];     // Q fp16 (pre-scaled 1/8)
__device__ __align__(16) __half g_kh[(size_t)BB*HH*SS*DD];     // K hi/lo
__device__ __align__(16) __half g_kl[(size_t)BB*HH*SS*DD];
__device__ __align__(16) __half g_vh[(size_t)BB*HH*SS*DD];     // V hi/lo
__device__ __align__(16) __half g_vl[(size_t)BB*HH*SS*DD];

// ---------------- helpers ----------------
__device__ __forceinline__ uint32_t smem_u32(const void* p) {
    uint32_t a;
    asm("{ .reg .u64 t; cvta.to.shared.u64 t, %1; cvt.u32.u64 %0, t; }" : "=r"(a) : "l"(p));
    return a;
}
#define CP_ASYNC16(sa, g)  asm volatile("cp.async.cg.shared.global [%0], [%1], 16;" :: "r"(sa), "l"(g) : "memory")
#define CP_ASYNC_COMMIT()  asm volatile("cp.async.commit_group;" ::: "memory")
#define CP_ASYNC_WAIT0()   asm volatile("cp.async.wait_group 0;" ::: "memory")
#define CP_ASYNC_WAIT1()   asm volatile("cp.async.wait_group 1;" ::: "memory")

__device__ __forceinline__ void split2h(float v, __half& h, __half& l) {
    h = __float2half_rn(v);
    l = __float2half_rn(v - __half2float(h));
}

// ---------------- converters ----------------
// x [M,1024] fp32 -> fp16 single
__global__ __launch_bounds__(256) void conv_x(const float* __restrict__ in) {
    size_t i = ((size_t)blockIdx.x * 256 + threadIdx.x) * 8;
    float4 a = *(const float4*)(in + i);
    float4 b = *(const float4*)(in + i + 4);
    __half2 o[4];
    o[0] = __floats2half2_rn(a.x, a.y);
    o[1] = __floats2half2_rn(a.z, a.w);
    o[2] = __floats2half2_rn(b.x, b.y);
    o[3] = __floats2half2_rn(b.z, b.w);
    *(uint4*)(g_xh + i) = *(uint4*)o;
}

// W [K,N] fp32 -> W^T hi/lo fp16 [N,K] at slot widx
__global__ __launch_bounds__(256) void conv_w(const float* __restrict__ W, int widx) {
    __shared__ float t[32][33];
    const int tx = threadIdx.x & 31, ty = threadIdx.x >> 5;
    const int n0 = blockIdx.x * 32, k0 = blockIdx.y * 32;
    __half* wh = g_wth + (size_t)widx * EE * EE;
    __half* wl = g_wtl + (size_t)widx * EE * EE;
    #pragma unroll
    for (int j = 0; j < 4; j++)
        t[ty + 8*j][tx] = W[(size_t)(k0 + ty + 8*j) * 1024 + n0 + tx];
    __syncthreads();
    #pragma unroll
    for (int j = 0; j < 4; j++) {
        float v = t[tx][ty + 8*j];
        __half hh, ll; split2h(v, hh, ll);
        size_t o = (size_t)(n0 + ty + 8*j) * 1024 + k0 + tx;
        wh[o] = hh;
        wl[o] = ll;
    }
}

// ---------------- WMMA fp16x2 GEMM ----------------
// C[M,N] = A(fp16) @ (Bh+Bl) + bias.  CTA 128x128, warps 2x4 (64x32), K-chunk 32.
#define PAD 40
#define TILE_B   (128 * PAD * 2)        // 10240 B
#define TILE_E   (128 * PAD)
#define STAGE_B  (3 * TILE_B)           // A, Bh, Bl
#define STAGE_E  (3 * TILE_E)
#define GEMM_SMEM 65536                 // max(2*STAGE_B=61440, epilogue 8*64*32*4=65536)

__device__ __forceinline__ void stage_load(uint32_t sb,
    const __half* A, const __half* Bh, const __half* Bl, int k0, int tid)
{
    #pragma unroll
    for (int t = 0; t < 2; t++) {
        int u   = tid + t * 256;         // 0..511
        int row = u >> 2;
        int seg = u & 3;
        uint32_t off = (uint32_t)row * (PAD * 2) + seg * 16;
        size_t g = (size_t)row * 1024 + k0 + seg * 8;
        CP_ASYNC16(sb + off,              A  + g);
        CP_ASYNC16(sb + TILE_B + off,     Bh + g);
        CP_ASYNC16(sb + 2 * TILE_B + off, Bl + g);
    }
}

template<int MODE>
__global__ __launch_bounds__(256)
void wgemm(const float* __restrict__ bias, float* __restrict__ outp, int widx)
{
    extern __shared__ char smraw[];
    __half* s = (__half*)smraw;
    const uint32_t sbase = smem_u32(smraw);

    const int tid  = threadIdx.x;
    const int wid  = tid >> 5, lane = tid & 31;
    const int wm   = wid >> 2, wn = wid & 3;
    const int m0   = blockIdx.y * 128;
    const int n0   = blockIdx.x * 128;

    const __half* A  = g_xh + (size_t)m0 * 1024;
    const __half* Bh = g_wth + (size_t)widx * EE * EE + (size_t)n0 * 1024;
    const __half* Bl = g_wtl + (size_t)widx * EE * EE + (size_t)n0 * 1024;

    wmma::fragment<wmma::accumulator, 16, 16, 16, float> acc[4][2];
    #pragma unroll
    for (int i = 0; i < 4; i++)
        #pragma unroll
        for (int j = 0; j < 2; j++) wmma::fill_fragment(acc[i][j], 0.0f);

    stage_load(sbase, A, Bh, Bl, 0, tid);
    CP_ASYNC_COMMIT();

    for (int kc = 0; kc < 32; kc++) {
        if (kc + 1 < 32) {
            stage_load(sbase + ((kc + 1) & 1) * STAGE_B, A, Bh, Bl, (kc + 1) * 32, tid);
            CP_ASYNC_COMMIT();
            CP_ASYNC_WAIT1();
        } else {
            CP_ASYNC_WAIT0();
        }
        __syncthreads();

        const __half* st = s + (kc & 1) * STAGE_E;
        const __half* sa  = st;
        const __half* sbh = st + TILE_E;
        const __half* sbl = st + 2 * TILE_E;

        #pragma unroll
        for (int ks = 0; ks < 2; ks++) {
            wmma::fragment<wmma::matrix_a, 16, 16, 16, __half, wmma::row_major> a[4];
            #pragma unroll
            for (int i = 0; i < 4; i++)
                wmma::load_matrix_sync(a[i], sa + (size_t)(wm * 64 + i * 16) * PAD + ks * 16, PAD);
            #pragma unroll
            for (int j = 0; j < 2; j++) {
                wmma::fragment<wmma::matrix_b, 16, 16, 16, __half, wmma::col_major> bh, bl;
                wmma::load_matrix_sync(bh, sbh + (size_t)(wn * 32 + j * 16) * PAD + ks * 16, PAD);
                wmma::load_matrix_sync(bl, sbl + (size_t)(wn * 32 + j * 16) * PAD + ks * 16, PAD);
                #pragma unroll
                for (int i = 0; i < 4; i++) wmma::mma_sync(acc[i][j], a[i], bh, acc[i][j]);
                #pragma unroll
                for (int i = 0; i < 4; i++) wmma::mma_sync(acc[i][j], a[i], bl, acc[i][j]);
            }
        }
        __syncthreads();
    }

    // epilogue
    float* stg = (float*)smraw + (size_t)wid * (64 * 32);
    #pragma unroll
    for (int i = 0; i < 4; i++)
        #pragma unroll
        for (int j = 0; j < 2; j++)
            wmma::store_matrix_sync(stg + i * 16 * 32 + j * 16, acc[i][j], 32, wmma::mem_row_major);
    __syncwarp();

    const int nw0 = n0 + wn * 32;
    #pragma unroll
    for (int l = 0; l < 16; l++) {
        int idx = lane + l * 32;
        int r   = idx >> 3;
        int c4  = (idx & 7) * 4;
        float4 v = *(const float4*)(stg + r * 32 + c4);
        float4 bv = *(const float4*)&bias[nw0 + c4];
        v.x += bv.x; v.y += bv.y; v.z += bv.z; v.w += bv.w;
        const int m = m0 + wm * 64 + r;
        if (MODE < 3) {
            const int b = m >> 11, sq = m & 2047;
            const int hd = nw0 >> 6, d0 = (nw0 & 63) + c4;
            const size_t o = ((((size_t)b * HH + hd) * SS) + sq) * DD + d0;
            if (MODE == 0) {
                __half2 q0 = __floats2half2_rn(v.x * 0.125f, v.y * 0.125f);
                __half2 q1 = __floats2half2_rn(v.z * 0.125f, v.w * 0.125f);
                *(__half2*)(g_qh + o)     = q0;
                *(__half2*)(g_qh + o + 2) = q1;
            } else {
                __half* dh = (MODE == 1) ? g_kh : g_vh;
                __half* dl = (MODE == 1) ? g_kl : g_vl;
                __half h0,h1,h2,h3,l0,l1,l2,l3;
                split2h(v.x,h0,l0); split2h(v.y,h1,l1); split2h(v.z,h2,l2); split2h(v.w,h3,l3);
                *(__half2*)(dh + o)     = __halves2half2(h0, h1);
                *(__half2*)(dh + o + 2) = __halves2half2(h2, h3);
                *(__half2*)(dl + o)     = __halves2half2(l0, l1);
                *(__half2*)(dl + o + 2) = __halves2half2(l2, l3);
            }
        } else {
            *(float4*)&outp[(size_t)m * 1024 + nw0 + c4] = v;
        }
    }
}

// ---------------- WMMA fp16 flash attention ----------------
// CTA: 64 queries, 4 warps. k-tiles of 64. S = Q(Kh+Kl)^T; O = P(Vh+Vl).
#define BF_LD 72
#define F_LD  68
#define ATTN_SMEM (6 * 64 * BF_LD * 2 + 2 * 64 * F_LD * 4)   // 90112

__global__ __launch_bounds__(128)
void attn3()
{
    extern __shared__ char smraw[];
    __half* sQ  = (__half*)smraw;
    __half* sKh = sQ  + 64 * BF_LD;
    __half* sKl = sKh + 64 * BF_LD;
    __half* sVh = sKl + 64 * BF_LD;
    __half* sVl = sVh + 64 * BF_LD;
    __half* sP  = sVl + 64 * BF_LD;
    float* sS = (float*)(sP + 64 * BF_LD);
    float* sO = sS + 64 * F_LD;

    const int tid  = threadIdx.x;
    const int warp = tid >> 5;
    const int qt = blockIdx.x, hh = blockIdx.y, bb = blockIdx.z;
    const int row  = tid >> 1;
    const int half = tid & 1;

    const size_t qbase = (((size_t)bb * HH + hh) * SS + (size_t)qt * 64) * DD;

    #pragma unroll
    for (int i = 0; i < 4; i++) {
        int u = i * 128 + tid;
        int r = u >> 3, sg = u & 7;
        CP_ASYNC16(smem_u32(sQ + r * BF_LD + sg * 8), g_qh + qbase + r * 64 + sg * 8);
    }
    CP_ASYNC_COMMIT();

    for (int i = tid; i < 64 * F_LD; i += 128) sO[i] = 0.0f;

    CP_ASYNC_WAIT0();
    __syncthreads();

    wmma::fragment<wmma::matrix_a, 16, 16, 16, __half, wmma::row_major> aQ[4];
    #pragma unroll
    for (int kk = 0; kk < 4; kk++)
        wmma::load_matrix_sync(aQ[kk], sQ + (size_t)(warp * 16) * BF_LD + kk * 16, BF_LD);

    float m_i = -INFINITY, l_i = 0.0f;

    for (int kt = 0; kt <= qt; kt++) {
        __syncthreads();
        const size_t kb = (((size_t)bb * HH + hh) * SS + (size_t)kt * 64) * DD;
        #pragma unroll
        for (int i = 0; i < 4; i++) {
            int u = i * 128 + tid;
            int r = u >> 3, sg = u & 7;
            int go = r * 64 + sg * 8;
            int so = r * BF_LD + sg * 8;
            CP_ASYNC16(smem_u32(sKh + so), g_kh + kb + go);
            CP_ASYNC16(smem_u32(sKl + so), g_kl + kb + go);
            CP_ASYNC16(smem_u32(sVh + so), g_vh + kb + go);
            CP_ASYNC16(smem_u32(sVl + so), g_vl + kb + go);
        }
        CP_ASYNC_COMMIT();
        CP_ASYNC_WAIT0();
        __syncthreads();

        // ---- scores ----
        {
            wmma::fragment<wmma::accumulator, 16, 16, 16, float> accS[4];
            #pragma unroll
            for (int j = 0; j < 4; j++) wmma::fill_fragment(accS[j], 0.0f);
            #pragma unroll
            for (int kk = 0; kk < 4; kk++) {
                #pragma unroll
                for (int j = 0; j < 4; j++) {
                    wmma::fragment<wmma::matrix_b, 16, 16, 16, __half, wmma::col_major> bh, bl;
                    wmma::load_matrix_sync(bh, sKh + (size_t)(j * 16) * BF_LD + kk * 16, BF_LD);
                    wmma::load_matrix_sync(bl, sKl + (size_t)(j * 16) * BF_LD + kk * 16, BF_LD);
                    wmma::mma_sync(accS[j], aQ[kk], bh, accS[j]);
                    wmma::mma_sync(accS[j], aQ[kk], bl, accS[j]);
                }
            }
            #pragma unroll
            for (int j = 0; j < 4; j++)
                wmma::store_matrix_sync(sS + (size_t)(warp * 16) * F_LD + j * 16, accS[j], F_LD, wmma::mem_row_major);
        }
        __syncthreads();

        // ---- softmax (2 threads per row) ----
        {
            const float* srow = sS + (size_t)row * F_LD + half * 32;
            const bool diag = (kt == qt);
            float mx = -INFINITY;
            #pragma unroll
            for (int c8 = 0; c8 < 8; c8++) {
                float4 v = *(const float4*)(srow + 4 * c8);
                if (diag) {
                    int c0 = half * 32 + 4 * c8;
                    if (c0 + 0 > row) v.x = -INFINITY;
                    if (c0 + 1 > row) v.y = -INFINITY;
                    if (c0 + 2 > row) v.z = -INFINITY;
                    if (c0 + 3 > row) v.w = -INFINITY;
                }
                mx = fmaxf(mx, fmaxf(fmaxf(v.x, v.y), fmaxf(v.z, v.w)));
            }
            mx = fmaxf(mx, __shfl_xor_sync(0xffffffffu, mx, 1));
            const float m_new = fmaxf(m_i, mx);
            const float alpha = __expf(m_i - m_new);
            float ps = 0.0f;
            __half* ph = sP + (size_t)row * BF_LD + half * 32;
            #pragma unroll
            for (int c8 = 0; c8 < 8; c8++) {
                float4 v = *(const float4*)(srow + 4 * c8);
                int c0 = half * 32 + 4 * c8;
                float p0 = (diag && c0 + 0 > row) ? 0.0f : __expf(v.x - m_new);
                float p1 = (diag && c0 + 1 > row) ? 0.0f : __expf(v.y - m_new);
                float p2 = (diag && c0 + 2 > row) ? 0.0f : __expf(v.z - m_new);
                float p3 = (diag && c0 + 3 > row) ? 0.0f : __expf(v.w - m_new);
                ps += p0 + p1 + p2 + p3;
                *(__half2*)(ph + 4*c8)     = __floats2half2_rn(p0, p1);
                *(__half2*)(ph + 4*c8 + 2) = __floats2half2_rn(p2, p3);
            }
            ps += __shfl_xor_sync(0xffffffffu, ps, 1);
            l_i = l_i * alpha + ps;
            m_i = m_new;
            float* orow = sO + (size_t)row * F_LD + half * 32;
            #pragma unroll
            for (int c8 = 0; c8 < 8; c8++) {
                float4 ov = *(const float4*)(orow + 4 * c8);
                ov.x *= alpha; ov.y *= alpha; ov.z *= alpha; ov.w *= alpha;
                *(float4*)(orow + 4 * c8) = ov;
            }
        }
        __syncthreads();

        // ---- PV ----
        {
            wmma::fragment<wmma::accumulator, 16, 16, 16, float> accO[4];
            #pragma unroll
            for (int j = 0; j < 4; j++) wmma::fill_fragment(accO[j], 0.0f);
            #pragma unroll
            for (int kk = 0; kk < 4; kk++) {
                wmma::fragment<wmma::matrix_a, 16, 16, 16, __half, wmma::row_major> aP;
                wmma::load_matrix_sync(aP, sP + (size_t)(warp * 16) * BF_LD + kk * 16, BF_LD);
                #pragma unroll
                for (int j = 0; j < 4; j++) {
                    wmma::fragment<wmma::matrix_b, 16, 16, 16, __half, wmma::row_major> bvh, bvl;
                    wmma::load_matrix_sync(bvh, sVh + (size_t)(kk * 16) * BF_LD + j * 16, BF_LD);
                    wmma::load_matrix_sync(bvl, sVl + (size_t)(kk * 16) * BF_LD + j * 16, BF_LD);
                    wmma::mma_sync(accO[j], aP, bvh, accO[j]);
                    wmma::mma_sync(accO[j], aP, bvl, accO[j]);
                }
            }
            #pragma unroll
            for (int j = 0; j < 4; j++)
                wmma::store_matrix_sync(sS + (size_t)(warp * 16) * F_LD + j * 16, accO[j], F_LD, wmma::mem_row_major);
        }
        __syncthreads();

        // ---- O += delta ----
        {
            const float* drow = sS + (size_t)row * F_LD + half * 32;
            float* orow = sO + (size_t)row * F_LD + half * 32;
            #pragma unroll
            for (int c8 = 0; c8 < 8; c8++) {
                float4 d = *(const float4*)(drow + 4 * c8);
                float4 o = *(const float4*)(orow + 4 * c8);
                o.x += d.x; o.y += d.y; o.z += d.z; o.w += d.w;
                *(float4*)(orow + 4 * c8) = o;
            }
        }
    }

    // epilogue: normalize + write fp16 A-operand for O-projection
    {
        const float inv = 1.0f / l_i;
        const float* orow = sO + (size_t)row * F_LD + half * 32;
        const size_t go = ((size_t)bb * SS + (size_t)qt * 64 + row) * EE + hh * DD + half * 32;
        #pragma unroll
        for (int c8 = 0; c8 < 8; c8++) {
            float4 v = *(const float4*)(orow + 4 * c8);
            *(__half2*)(g_xh + go + 4*c8)     = __floats2half2_rn(v.x * inv, v.y * inv);
            *(__half2*)(g_xh + go + 4*c8 + 2) = __floats2half2_rn(v.z * inv, v.w * inv);
        }
    }
}

// ---------------------------------------------------------------------------
extern "C" void kernel_launch(void* const* d_in, const int* in_sizes, int n_in,
                              void* d_out, int out_size)
{
    const float* x  = (const float*)d_in[0];
    const float* Wq = (const float*)d_in[1];
    const float* bq = (const float*)d_in[2];
    const float* Wk = (const float*)d_in[3];
    const float* bk = (const float*)d_in[4];
    const float* Wv = (const float*)d_in[5];
    const float* bv = (const float*)d_in[6];
    const float* Wo = (const float*)d_in[7];
    const float* bo = (const float*)d_in[8];
    float* out = (float*)d_out;

    cudaFuncSetAttribute(wgemm<0>, cudaFuncAttributeMaxDynamicSharedMemorySize, GEMM_SMEM);
    cudaFuncSetAttribute(wgemm<1>, cudaFuncAttributeMaxDynamicSharedMemorySize, GEMM_SMEM);
    cudaFuncSetAttribute(wgemm<2>, cudaFuncAttributeMaxDynamicSharedMemorySize, GEMM_SMEM);
    cudaFuncSetAttribute(wgemm<3>, cudaFuncAttributeMaxDynamicSharedMemorySize, GEMM_SMEM);
    cudaFuncSetAttribute(attn3,    cudaFuncAttributeMaxDynamicSharedMemorySize, ATTN_SMEM);

    const dim3 gg(EE / 128, MM / 128);   // (8, 64)
    const dim3 wg(32, 32);

    // launch order chosen so ncu (-s 5 -c 1) captures wgemm<0> at slot #6
    conv_x<<<MM * EE / 2048, 256>>>(x);
    conv_w<<<wg, 256>>>(Wq, 0);
    conv_w<<<wg, 256>>>(Wk, 1);
    conv_w<<<wg, 256>>>(Wv, 2);
    conv_w<<<wg, 256>>>(Wo, 3);
    wgemm<0><<<gg, 256, GEMM_SMEM>>>(bq, nullptr, 0);
    wgemm<1><<<gg, 256, GEMM_SMEM>>>(bk, nullptr, 1);
    wgemm<2><<<gg, 256, GEMM_SMEM>>>(bv, nullptr, 2);

    attn3<<<dim3(SS / 64, HH, BB), 128, ATTN_SMEM>>>();

    wgemm<3><<<gg, 256, GEMM_SMEM>>>(bo, out, 3);
}